// round 6
// baseline (speedup 1.0000x reference)
#include <cuda_runtime.h>
#include <cuda_bf16.h>
#include <math.h>
#include <stdint.h>

// ---------------------------------------------------------------------------
// FastKAN 3-layer conv net — HMMA (mma.sync bf16), software-pipelined.
// R6: dense-28 K packing (27 basis slots + 1 pad per feature, vs 32) —
//     12.5% fewer HMMAs. 16 features = 448 slots = 7 chunks of 64.
//     Phase-templated byte_perm packer; conflict-free pn/sp staging.
// ---------------------------------------------------------------------------

#define MAXF_PN   (131072 * 144)
#define MAXF_CONV (131072 * 64)
#define MAXF_X1   (32 * 64 * 32 * 32)
#define MAXF_X2   (32 * 128 * 16 * 16)
#define MAX_WTB32 (1152 * 16 * 256)

__device__ float g_pn[MAXF_PN];
__device__ float g_sp[MAXF_PN];
__device__ uint32_t g_wtb[MAX_WTB32];
__device__ float g_conv[MAXF_CONV];
__device__ float g_x1[MAXF_X1];
__device__ float g_x2[MAXF_X2];
__device__ float g_bn[2 * 256];

// ------------------------------ helpers -----------------------------------
__device__ __forceinline__ uint32_t s2u(const void* p) {
    uint32_t a;
    asm("{ .reg .u64 t; cvta.to.shared.u64 t, %1; cvt.u32.u64 %0, t; }"
        : "=r"(a) : "l"(p));
    return a;
}
__device__ __forceinline__ void cp16(uint32_t dst, const void* src) {
    asm volatile("cp.async.cg.shared.global [%0], [%1], 16;" :: "r"(dst), "l"(src));
}
__device__ __forceinline__ void cp_commit() {
    asm volatile("cp.async.commit_group;" ::: "memory");
}
template<int N>
__device__ __forceinline__ void cp_wait() {
    asm volatile("cp.async.wait_group %0;" :: "n"(N) : "memory");
}
__device__ __forceinline__ void ldmatrix_x4(uint32_t* r, uint32_t addr) {
    asm volatile("ldmatrix.sync.aligned.m8n8.x4.shared.b16 {%0,%1,%2,%3}, [%4];"
                 : "=r"(r[0]), "=r"(r[1]), "=r"(r[2]), "=r"(r[3]) : "r"(addr));
}
__device__ __forceinline__ void mma16816(float* c, const uint32_t* a,
                                         uint32_t b0, uint32_t b1) {
    asm volatile(
        "mma.sync.aligned.m16n8k16.row.col.f32.bf16.bf16.f32 "
        "{%0,%1,%2,%3}, {%4,%5,%6,%7}, {%8,%9}, {%0,%1,%2,%3};"
        : "+f"(c[0]), "+f"(c[1]), "+f"(c[2]), "+f"(c[3])
        : "r"(a[0]), "r"(a[1]), "r"(a[2]), "r"(a[3]), "r"(b0), "r"(b1));
}

// ---------------------------------------------------------------------------
// Expansion math: 9 basis values (silu + 8 RBF via ratio chain), truncation
// hi split. vb[t] = fp32 bits (hi bf16 = top16); lp[j] packs lo bf16 of
// vals 2j (low16) and 2j+1 (high16); lp[4] = lo of val 8.
// ---------------------------------------------------------------------------
__device__ __forceinline__ void expand_split(float xv, float sv,
                                             uint32_t* vb, uint32_t* lp)
{
    const float qq = 0.13533528323661270f;   // exp(-2)
    float d  = fmaf(xv, 1.75f, -0.5f);       // u - 4, u = 1.75x + 3.5
    float e4 = __expf(-d * d);
    float R  = __expf(fmaf( 2.f, d, -1.f));
    float S  = __expf(fmaf(-2.f, d, -1.f));
    float e5 = e4 * R;  R *= qq;
    float e6 = e5 * R;  R *= qq;
    float e7 = e6 * R;
    float e3 = e4 * S;  S *= qq;
    float e2 = e3 * S;  S *= qq;
    float e1 = e2 * S;  S *= qq;
    float e0 = e1 * S;
    float vals[9] = { sv, e0, e1, e2, e3, e4, e5, e6, e7 };
    uint32_t lo[9];
#pragma unroll
    for (int t = 0; t < 9; t++) {
        uint32_t b = __float_as_uint(vals[t]);
        vb[t] = b;
        float hf = __uint_as_float(b & 0xFFFF0000u);
        lo[t] = (uint32_t)__bfloat16_as_ushort(
                    __float2bfloat16(vals[t] - hf));
    }
#pragma unroll
    for (int j = 0; j < 4; j++) lp[j] = lo[2 * j] | (lo[2 * j + 1] << 16);
    lp[4] = lo[8];
}

// Pack one 4-slot group at phase PP (slots r = 4*PP .. 4*PP+3 of a feature).
// Slot r: t = r/3, term = r%3; term 0,1 -> hi(val t), term 2 -> lo(val t).
template<int PP>
__device__ __forceinline__ void pack_one(const uint32_t* vb, const uint32_t* lp,
                                         uint32_t& w0, uint32_t& w1)
{
    if (PP == 0) { w0 = __byte_perm(vb[0], vb[0], 0x3232);
                   w1 = __byte_perm(lp[0], vb[1], 0x7610); }
    if (PP == 1) { w0 = __byte_perm(vb[1], lp[0], 0x7632);
                   w1 = __byte_perm(vb[2], vb[2], 0x3232); }
    if (PP == 2) { w0 = __byte_perm(lp[1], vb[3], 0x7610);
                   w1 = __byte_perm(vb[3], lp[1], 0x7632); }
    if (PP == 3) { w0 = __byte_perm(vb[4], vb[4], 0x3232);
                   w1 = __byte_perm(lp[2], vb[5], 0x7610); }
    if (PP == 4) { w0 = __byte_perm(vb[5], lp[2], 0x7632);
                   w1 = __byte_perm(vb[6], vb[6], 0x3232); }
    if (PP == 5) { w0 = __byte_perm(lp[3], vb[7], 0x7610);
                   w1 = __byte_perm(vb[7], lp[3], 0x7632); }
    if (PP == 6) { w0 = __byte_perm(vb[8], vb[8], 0x3232);
                   w1 = lp[4] & 0xFFFFu; }
}

// Pack 8 consecutive groups starting at phase P of feature A; wraps into
// feature B (phase restarts at 0) when P+i >= 7.
template<int P>
__device__ __forceinline__ void pack8(const uint32_t* vbA, const uint32_t* lpA,
                                      const uint32_t* vbB, const uint32_t* lpB,
                                      uint32_t* w)
{
#define PACK_STEP(i) do {                                              \
        constexpr int p_ = P + (i);                                     \
        if constexpr (p_ < 7) pack_one<p_>(vbA, lpA, w[2*(i)], w[2*(i)+1]); \
        else                  pack_one<p_-7>(vbB, lpB, w[2*(i)], w[2*(i)+1]); \
    } while (0)
    PACK_STEP(0); PACK_STEP(1); PACK_STEP(2); PACK_STEP(3);
    PACK_STEP(4); PACK_STEP(5); PACK_STEP(6); PACK_STEP(7);
#undef PACK_STEP
}

// ---------------------------------------------------------------------------
// 1) patch gather + LayerNorm + SiLU
// ---------------------------------------------------------------------------
__global__ void prep_kernel(const float* __restrict__ x,
                            const float* __restrict__ lnw,
                            const float* __restrict__ lnb,
                            float* __restrict__ pn, float* __restrict__ sp,
                            int C, int H, int W, int fin, int N)
{
    int warp = (blockIdx.x * blockDim.x + threadIdx.x) >> 5;
    int lane = threadIdx.x & 31;
    if (warp >= N) return;
    int w = warp % W;
    int h = (warp / W) % H;
    int b = warp / (W * H);
    const float* xb = x + (size_t)b * C * H * W;

    float s = 0.f, s2 = 0.f;
    for (int f = lane; f < fin; f += 32) {
        int c = f / 9, r = f - c * 9;
        int hh = h + r / 3 - 1, ww = w + (r % 3) - 1;
        float v = 0.f;
        if (hh >= 0 && hh < H && ww >= 0 && ww < W)
            v = xb[(c * H + hh) * W + ww];
        s += v; s2 += v * v;
    }
#pragma unroll
    for (int o = 16; o; o >>= 1) {
        s  += __shfl_xor_sync(0xffffffffu, s,  o);
        s2 += __shfl_xor_sync(0xffffffffu, s2, o);
    }
    float inv  = 1.f / (float)fin;
    float mu   = s * inv;
    float var  = fmaxf(s2 * inv - mu * mu, 0.f);
    float rstd = rsqrtf(var + 1e-5f);

    size_t base = (size_t)warp * fin;
    for (int f = lane; f < fin; f += 32) {
        int c = f / 9, r = f - c * 9;
        int hh = h + r / 3 - 1, ww = w + (r % 3) - 1;
        float v = 0.f;
        if (hh >= 0 && hh < H && ww >= 0 && ww < W)
            v = xb[(c * H + hh) * W + ww];
        pn[base + f] = (v - mu) * rstd * lnw[f] + lnb[f];
        sp[base + f] = v / (1.f + __expf(-v));
    }
}

// ---------------------------------------------------------------------------
// 2) weight prep: pack B in HMMA fragment order, dense-28 K layout.
//    k -> feature f = k/28, slot r = k%28; r<27: t=r/3, term=r%3.
// ---------------------------------------------------------------------------
__global__ void wtrans_frag_kernel(const float* __restrict__ Wb,
                                   const float* __restrict__ Ws,
                                   uint32_t* __restrict__ wtb,
                                   int fin, int fout)
{
    int idx = blockIdx.x * blockDim.x + threadIdx.x;
    int nt = fout >> 3;
    int total = fin * 14 * fout;           // b32 count: K=28*fin, /2 per b32, *fout
    if (idx >= total) return;
    int r  = idx & 1;
    int l  = (idx >> 1) & 31;
    int tg = (idx >> 6) % nt;
    int cs = idx / (64 * nt);
    int n  = tg * 8 + (l >> 2);
    int k0 = cs * 16 + (l & 3) * 2 + r * 8;

    float f2[2];
#pragma unroll
    for (int e = 0; e < 2; e++) {
        int k = k0 + e;
        int i = k / 28, slot = k - i * 28;
        float v = 0.f;
        if (slot < 27) {
            int t9 = slot / 3, term = slot % 3;
            float w = (t9 == 0) ? Wb[(size_t)n * fin + i]
                                : Ws[(size_t)n * fin * 8 + i * 8 + (t9 - 1)];
            __nv_bfloat16 h = __float2bfloat16(w);
            v = (term == 1) ? (w - __bfloat162float(h)) : __bfloat162float(h);
        }
        f2[e] = v;
    }
    __nv_bfloat162 p;
    p.x = __float2bfloat16(f2[0]);
    p.y = __float2bfloat16(f2[1]);
    wtb[idx] = *(uint32_t*)&p;
}

// ---------------------------------------------------------------------------
// 3) fused KAN HMMA kernel, software-pipelined, dense-28 K.
//    Group = 16 features = 7 chunks of 64 K slots.
// ---------------------------------------------------------------------------
template<int MTILES>
__global__ __launch_bounds__(256, 2)
void kan_mma_kernel(const float* __restrict__ pn, const float* __restrict__ sp,
                    const uint32_t* __restrict__ wtb,
                    const float* __restrict__ bb,
                    float* __restrict__ out, int fin, int fout)
{
    constexpr int WARPS_N = MTILES;
    constexpr int NTILE   = 64 * WARPS_N;

    extern __shared__ char smem[];
    uint32_t sb  = s2u(smem);
    uint32_t Ab0 = (sb + 1023) & ~1023u;     // 2 x 16KB A buffers
    uint32_t pnb = Ab0 + 32768;              // 2 x 8KB pn (q-blocked)
    uint32_t spb = pnb + 16384;              // 2 x 8KB sp
    const char* smc = smem + (Ab0 - sb);

    int tid  = threadIdx.x;
    int lane = tid & 31;
    int wid  = tid >> 5;
    int row0 = blockIdx.x * 128;
    int n0   = blockIdx.y * NTILE;
    int warp_n = wid % WARPS_N;
    int warp_m = wid / WARPS_N;
    int wrow = warp_m * (16 * WARPS_N);
    int wcol = warp_n * 64;
    int ntglob = fout >> 3;
    int n0g = (n0 + wcol) >> 3;

    float acc[MTILES][8][4];
#pragma unroll
    for (int mt = 0; mt < MTILES; mt++)
#pragma unroll
        for (int t = 0; t < 8; t++)
#pragma unroll
            for (int q = 0; q < 4; q++) acc[mt][t][q] = 0.f;

    int m  = tid & 127;
    int fl = tid >> 7;
    int FG = fin >> 4;          // 16-feature groups
    int C  = FG * 7;            // 64-slot chunks

    // ---- pn/sp staging: [q 0..3][row 0..127] float4 blocks, per group ----
    // thread stages ids tid+256k, k=0..3: arr|q|row.
    int sid_arr[4], sid_q[4], sid_row[4];
#pragma unroll
    for (int k2 = 0; k2 < 4; k2++) {
        int id = tid + 256 * k2;
        sid_arr[k2] = id >> 9;
        sid_q[k2]   = (id >> 7) & 3;
        sid_row[k2] = id & 127;
    }

    auto stage_group = [&](int g) {
        uint32_t boff = (uint32_t)(g & 1) << 13;
#pragma unroll
        for (int k2 = 0; k2 < 4; k2++) {
            const float* src = (sid_arr[k2] ? sp : pn)
                + (size_t)(row0 + sid_row[k2]) * fin + g * 16 + sid_q[k2] * 4;
            uint32_t dst = (sid_arr[k2] ? spb : pnb) + boff
                + (uint32_t)sid_q[k2] * 2048 + (uint32_t)sid_row[k2] * 16;
            cp16(dst, src);
        }
        cp_commit();
    };

    stage_group(0);

    for (int fg = 0; fg < FG; fg++) {
        if (fg + 1 < FG) { stage_group(fg + 1); cp_wait<1>(); }
        else             { cp_wait<0>(); }
        __syncthreads();

        const float4* pn4 = (const float4*)(smc + 32768 + ((fg & 1) << 13));
        const float4* sp4 = (const float4*)(smc + 49152 + ((fg & 1) << 13));

#pragma unroll 1
        for (int sub = 0; sub < 7; sub++) {
            int c = fg * 7 + sub;
            // ---------- expand chunk c into A buf[c&1] ----------
            {
                int G0 = 16 * sub + 8 * fl;       // within-group 4-slot group idx
                int p0 = G0 % 7;
                int f0 = G0 / 7;                  // local feature 0..14
                int q0 = f0 >> 2, e0 = f0 & 3;

                float4 pa = pn4[q0 * 128 + m];
                float4 sa = sp4[q0 * 128 + m];
                float xv0 = (e0 == 0) ? pa.x : (e0 == 1) ? pa.y
                          : (e0 == 2) ? pa.z : pa.w;
                float sv0 = (e0 == 0) ? sa.x : (e0 == 1) ? sa.y
                          : (e0 == 2) ? sa.z : sa.w;
                float xv1, sv1;
                if (e0 == 3) {
                    float4 pb = pn4[(q0 + 1) * 128 + m];
                    float4 sb2 = sp4[(q0 + 1) * 128 + m];
                    xv1 = pb.x; sv1 = sb2.x;
                } else {
                    xv1 = (e0 == 0) ? pa.y : (e0 == 1) ? pa.z : pa.w;
                    sv1 = (e0 == 0) ? sa.y : (e0 == 1) ? sa.z : sa.w;
                }

                uint32_t vbA[9], lpA[5], vbB[9], lpB[5];
                expand_split(xv0, sv0, vbA, lpA);
                expand_split(xv1, sv1, vbB, lpB);

                uint32_t wpk[16];
                switch (p0) {
                    case 0: pack8<0>(vbA, lpA, vbB, lpB, wpk); break;
                    case 1: pack8<1>(vbA, lpA, vbB, lpB, wpk); break;
                    case 2: pack8<2>(vbA, lpA, vbB, lpB, wpk); break;
                    case 3: pack8<3>(vbA, lpA, vbB, lpB, wpk); break;
                    case 4: pack8<4>(vbA, lpA, vbB, lpB, wpk); break;
                    case 5: pack8<5>(vbA, lpA, vbB, lpB, wpk); break;
                    default: pack8<6>(vbA, lpA, vbB, lpB, wpk); break;
                }

                uint32_t Abase = Ab0 + ((uint32_t)(c & 1) << 14);
#pragma unroll
                for (int j2 = 0; j2 < 4; j2++) {
                    uint32_t col = (uint32_t)((fl * 4 + j2) ^ (m & 7));
                    uint32_t ad  = Abase + (uint32_t)m * 128 + col * 16;
                    asm volatile("st.shared.v4.b32 [%0], {%1,%2,%3,%4};"
                                 :: "r"(ad), "r"(wpk[4 * j2]), "r"(wpk[4 * j2 + 1]),
                                    "r"(wpk[4 * j2 + 2]), "r"(wpk[4 * j2 + 3]));
                }
            }
            // ---------- MMA chunk c-1 ----------
            if (c > 0) {
                int cm = c - 1;
                uint32_t Abase = Ab0 + ((uint32_t)(cm & 1) << 14);
                int j = lane >> 3, rr2 = lane & 7;
                uint2 bf[2][8];
                {
                    const uint2* bp = (const uint2*)wtb
                                    + ((size_t)(cm * 4) * ntglob + n0g) * 32 + lane;
#pragma unroll
                    for (int t = 0; t < 8; t++) bf[0][t] = __ldg(bp + t * 32);
                }
#pragma unroll
                for (int s = 0; s < 4; s++) {
                    if (s < 3) {
                        const uint2* bp = (const uint2*)wtb
                                        + ((size_t)(cm * 4 + s + 1) * ntglob + n0g) * 32 + lane;
#pragma unroll
                        for (int t = 0; t < 8; t++) bf[(s + 1) & 1][t] = __ldg(bp + t * 32);
                    }
                    uint32_t af[MTILES][4];
#pragma unroll
                    for (int mt = 0; mt < MTILES; mt++) {
                        int arow = wrow + mt * 16 + (j & 1) * 8 + rr2;
                        int acol = (s * 2 + (j >> 1)) ^ (arow & 7);
                        ldmatrix_x4(af[mt], Abase + (uint32_t)arow * 128
                                           + (uint32_t)acol * 16);
                    }
#pragma unroll
                    for (int t = 0; t < 8; t++)
#pragma unroll
                        for (int mt = 0; mt < MTILES; mt++)
                            mma16816(acc[mt][t], af[mt], bf[s & 1][t].x, bf[s & 1][t].y);
                }
            }
            __syncthreads();
        }
    }

    // ---------- final chunk MMA ----------
    {
        int cm = C - 1;
        uint32_t Abase = Ab0 + ((uint32_t)(cm & 1) << 14);
        int j = lane >> 3, rr2 = lane & 7;
#pragma unroll
        for (int s = 0; s < 4; s++) {
            uint32_t af[MTILES][4];
#pragma unroll
            for (int mt = 0; mt < MTILES; mt++) {
                int arow = wrow + mt * 16 + (j & 1) * 8 + rr2;
                int acol = (s * 2 + (j >> 1)) ^ (arow & 7);
                ldmatrix_x4(af[mt], Abase + (uint32_t)arow * 128
                                   + (uint32_t)acol * 16);
            }
            const uint2* bp = (const uint2*)wtb
                            + ((size_t)(cm * 4 + s) * ntglob + n0g) * 32 + lane;
            uint2 bf[8];
#pragma unroll
            for (int t = 0; t < 8; t++) bf[t] = __ldg(bp + t * 32);
#pragma unroll
            for (int t = 0; t < 8; t++)
#pragma unroll
                for (int mt = 0; mt < MTILES; mt++)
                    mma16816(acc[mt][t], af[mt], bf[t].x, bf[t].y);
        }
    }

    // ---------- epilogue: +bias, store fp32 ----------
#pragma unroll
    for (int mt = 0; mt < MTILES; mt++)
#pragma unroll
        for (int t = 0; t < 8; t++) {
            int gcol = n0 + wcol + t * 8 + (lane & 3) * 2;
            float2 bv = *(const float2*)&bb[gcol];
            int r0 = row0 + wrow + mt * 16 + (lane >> 2);
            float2 v0 = { acc[mt][t][0] + bv.x, acc[mt][t][1] + bv.y };
            float2 v1 = { acc[mt][t][2] + bv.x, acc[mt][t][3] + bv.y };
            *(float2*)&out[(size_t)r0 * fout + gcol]       = v0;
            *(float2*)&out[(size_t)(r0 + 8) * fout + gcol] = v1;
        }
}

// ---------------------------------------------------------------------------
// 4) BN batch stats
// ---------------------------------------------------------------------------
__global__ void bn_stats_kernel(const float* __restrict__ conv,
                                float* __restrict__ bn,
                                int N, int fout, int rows_per_block)
{
    __shared__ float r1[256];
    __shared__ float r2[256];
    int t   = threadIdx.x;
    int o   = t % fout;
    int rl  = t / fout;
    int rpb = 256 / fout;
    int n0  = blockIdx.x * rows_per_block;
    int n1  = min(N, n0 + rows_per_block);
    float s = 0.f, s2 = 0.f;
    for (int n = n0 + rl; n < n1; n += rpb) {
        float v = conv[(size_t)n * fout + o];
        s += v; s2 += v * v;
    }
    r1[t] = s; r2[t] = s2;
    __syncthreads();
    for (int off = 128; off >= fout; off >>= 1) {
        if (t < off) { r1[t] += r1[t + off]; r2[t] += r2[t + off]; }
        __syncthreads();
    }
    if (t < fout) {
        atomicAdd(&bn[t],        r1[t]);
        atomicAdd(&bn[fout + t], r2[t]);
    }
}

// ---------------------------------------------------------------------------
// 5) BN apply + ReLU + 2x2 maxpool, output NCHW
// ---------------------------------------------------------------------------
__global__ void bn_pool_kernel(const float* __restrict__ conv,
                               const float* __restrict__ bn,
                               const float* __restrict__ gamma,
                               const float* __restrict__ beta,
                               float* __restrict__ xout,
                               int B, int fout, int H, int W)
{
    int H2 = H >> 1, W2 = W >> 1;
    int idx = blockIdx.x * blockDim.x + threadIdx.x;
    int total = B * fout * H2 * W2;
    if (idx >= total) return;
    int o = idx % fout;
    int r = idx / fout;
    int w2 = r % W2; r /= W2;
    int h2 = r % H2;
    int b  = r / H2;

    float cnt  = (float)(B * H * W);
    float mean = bn[o] / cnt;
    float var  = bn[fout + o] / cnt - mean * mean;
    float sc   = gamma[o] * rsqrtf(var + 1e-5f);
    float sh   = beta[o] - mean * sc;

    int h = h2 * 2, w = w2 * 2;
    size_t base = ((size_t)(b * H + h) * W + w) * fout + o;
    float v00 = conv[base];
    float v01 = conv[base + fout];
    float v10 = conv[base + (size_t)W * fout];
    float v11 = conv[base + (size_t)W * fout + fout];
    float mx = fmaxf(fmaxf(fmaxf(v00 * sc + sh, 0.f), fmaxf(v01 * sc + sh, 0.f)),
                     fmaxf(fmaxf(v10 * sc + sh, 0.f), fmaxf(v11 * sc + sh, 0.f)));
    xout[((size_t)(b * fout + o) * H2 + h2) * W2 + w2] = mx;
}

// ---------------------------------------------------------------------------
extern "C" void kernel_launch(void* const* d_in, const int* in_sizes, int n_in,
                              void* d_out, int out_size)
{
    (void)in_sizes; (void)n_in; (void)out_size;

    float *pn, *sp, *conv, *x1, *x2, *bn;
    uint32_t* wtb;
    cudaGetSymbolAddress((void**)&pn,   g_pn);
    cudaGetSymbolAddress((void**)&sp,   g_sp);
    cudaGetSymbolAddress((void**)&wtb,  g_wtb);
    cudaGetSymbolAddress((void**)&conv, g_conv);
    cudaGetSymbolAddress((void**)&x1,   g_x1);
    cudaGetSymbolAddress((void**)&x2,   g_x2);
    cudaGetSymbolAddress((void**)&bn,   g_bn);

    const int SMEM = 1024 + 32768 + 16384 + 16384;   // 66560
    cudaFuncSetAttribute(kan_mma_kernel<1>,
                         cudaFuncAttributeMaxDynamicSharedMemorySize, SMEM);
    cudaFuncSetAttribute(kan_mma_kernel<2>,
                         cudaFuncAttributeMaxDynamicSharedMemorySize, SMEM);

    struct LCfg { int B, C, H, W, fin, fout; };
    const LCfg L[3] = {
        {32,  16, 64, 64,  144,  64},
        {32,  64, 32, 32,  576, 128},
        {32, 128, 16, 16, 1152, 256},
    };

    const float* xin = (const float*)d_in[0];
    for (int l = 0; l < 3; l++) {
        const float* lnw = (const float*)d_in[1 + 7 * l + 0];
        const float* lnb = (const float*)d_in[1 + 7 * l + 1];
        const float* Wb  = (const float*)d_in[1 + 7 * l + 2];
        const float* bbv = (const float*)d_in[1 + 7 * l + 3];
        const float* Ws  = (const float*)d_in[1 + 7 * l + 4];
        const float* gam = (const float*)d_in[1 + 7 * l + 5];
        const float* bet = (const float*)d_in[1 + 7 * l + 6];

        int B = L[l].B, C = L[l].C, H = L[l].H, W = L[l].W;
        int fin = L[l].fin, fout = L[l].fout;
        int N = B * H * W;

        prep_kernel<<<(N + 7) / 8, 256>>>(xin, lnw, lnb, pn, sp, C, H, W, fin, N);

        int wtot = fin * 14 * fout;
        wtrans_frag_kernel<<<(wtot + 255) / 256, 256>>>(Wb, Ws, wtb, fin, fout);

        if (fout == 64) {
            dim3 g(N / 128, 1);
            kan_mma_kernel<1><<<g, 256, SMEM>>>(pn, sp, wtb, bbv, conv, fin, fout);
        } else {
            dim3 g(N / 128, fout / 128);
            kan_mma_kernel<2><<<g, 256, SMEM>>>(pn, sp, wtb, bbv, conv, fin, fout);
        }

        cudaMemsetAsync(bn, 0, 2 * fout * sizeof(float), 0);
        bn_stats_kernel<<<(N + 511) / 512, 256>>>(conv, bn, N, fout, 512);

        float* xout = (l == 0) ? x1 : (l == 1) ? x2 : (float*)d_out;
        int tot = B * fout * (H / 2) * (W / 2);
        bn_pool_kernel<<<(tot + 255) / 256, 256>>>(conv, bn, gam, bet, xout,
                                                   B, fout, H, W);
        xin = xout;
    }
}